// round 8
// baseline (speedup 1.0000x reference)
#include <cuda_runtime.h>
#include <math.h>

#define GRID 128
#define NT   256
#define Bz   32
#define Sz   256
#define Iz   256
#define Hz   512
#define Nz   128
#define Cz   64
#define Oz   256
#define Pz   268
#define KV   832
#define KVP  836
#define WBP  516
#define MP   68
#define GBP  17      // gb4 row pad
#define EPSF 1e-8f

struct GState {
    unsigned bar_cnt;
    unsigned bar_gen;
    unsigned pad[30];
    float h[Bz * Hz];
    float r[Bz * Cz];
    float p[Bz * Pz];
    float outh[Bz * Oz];
};
__device__ GState gs;

struct Smem {
    float WA[32 * KVP];      // gate weight rows [Wih|Whh], padded
    float V[16 * KVP];       // [x|r|h] for this CTA's 16 batches
    float WB[9 * WBP];       // head/out rows
    float gb4[4 * 32 * GBP]; // GEMM k-partials; reused as rbuf[c*32+b] in D
    float M[Nz * MP];
    float Mn[Nz];
    float wr[Nz];
    float ww[Nz];
    float t1[Nz];
    float pb[Pz];
    float kr[Cz]; float kw[Cz]; float eb[Cz]; float ab[Cz];
    float cst[8 * 16];
    float bA[32];
    float bB[9];
    float WoR[2 * Cz];
    float sc[16];
    float red[8];
};

extern __shared__ __align__(16) unsigned char smraw[];

__device__ __forceinline__ float sg_(float x) { return 1.f / (1.f + expf(-x)); }
__device__ __forceinline__ float sp_(float x) { return (x > 20.f) ? x : log1pf(expf(x)); }

__device__ __forceinline__ void gbar(unsigned gen0, unsigned &nb) {
    nb++;
    __syncthreads();
    if (threadIdx.x == 0) {
        __threadfence();
        unsigned target = gen0 + nb;
        unsigned old = atomicInc(&gs.bar_cnt, GRID - 1u);
        if (old == GRID - 1u) {
            atomicExch(&gs.bar_gen, target);
        } else {
            while ((int)(*((volatile unsigned*)&gs.bar_gen) - target) < 0) {}
        }
        __threadfence();
    }
    __syncthreads();
}

__device__ __forceinline__ float blk_max128(float v, Smem* s, int tid) {
    #pragma unroll
    for (int o = 16; o > 0; o >>= 1) v = fmaxf(v, __shfl_xor_sync(0xffffffffu, v, o));
    if (tid < 128 && (tid & 31) == 0) s->red[tid >> 5] = v;
    __syncthreads();
    float m = fmaxf(fmaxf(s->red[0], s->red[1]), fmaxf(s->red[2], s->red[3]));
    __syncthreads();
    return m;
}
__device__ __forceinline__ float blk_sum128(float v, Smem* s, int tid) {
    #pragma unroll
    for (int o = 16; o > 0; o >>= 1) v += __shfl_xor_sync(0xffffffffu, v, o);
    if (tid < 128 && (tid & 31) == 0) s->red[tid >> 5] = v;
    __syncthreads();
    float m = s->red[0] + s->red[1] + s->red[2] + s->red[3];
    __syncthreads();
    return m;
}

__global__ void __launch_bounds__(NT, 1)
ntm_kernel(const float* __restrict__ X,
           const float* __restrict__ Wih, const float* __restrict__ Whh,
           const float* __restrict__ bl,
           const float* __restrict__ Whd, const float* __restrict__ bhd,
           const float* __restrict__ Wout, const float* __restrict__ bout,
           float* __restrict__ Y)
{
    Smem* s = (Smem*)smraw;
    const int tid = threadIdx.x, bx = blockIdx.x;
    const int RG = bx >> 1, BH = bx & 1, b0 = BH * 16;

    // ---------------- one-time staging ----------------
    for (int rr = 0; rr < 32; rr++) {
        int gr = (rr >> 3) * Hz + RG * 8 + (rr & 7);
        for (int k = tid; k < KV; k += NT)
            s->WA[rr * KVP + k] = (k < 320) ? Wih[gr * 320 + k] : Whh[gr * Hz + (k - 320)];
    }
    if (tid < 32) {
        int gr = (tid >> 3) * Hz + RG * 8 + (tid & 7);
        s->bA[tid] = bl[gr];
    }
    const int base = RG * 9;
    const int cnt = (base >= 524) ? 0 : ((524 - base < 9) ? (524 - base) : 9);
    for (int rr = 0; rr < cnt; rr++) {
        int gr = base + rr;
        for (int k = tid; k < Hz; k += NT)
            s->WB[rr * WBP + k] = (gr < Pz) ? Whd[gr * Hz + k] : Wout[(gr - Pz) * 576 + k];
    }
    if (tid < cnt) {
        int gr = base + tid;
        s->bB[tid] = (gr < Pz) ? bhd[gr] : bout[gr - Pz];
    }
    for (int i = tid; i < 2 * Cz; i += NT)
        s->WoR[i] = Wout[(bx * 2 + (i >> 6)) * 576 + 512 + (i & 63)];
    for (int i = tid; i < 16 * KVP; i += NT) s->V[i] = 0.f;
    if (tid < 128) s->cst[tid] = 0.f;
    if (bx < Bz) {
        for (int i = tid; i < Nz * Cz; i += NT) s->M[(i >> 6) * MP + (i & 63)] = 0.01f;
        if (tid < Nz) {
            float w0 = (tid == 0) ? 1.f : 0.f;
            s->wr[tid] = w0; s->ww[tid] = w0; s->Mn[tid] = 0.08f;
        }
    }
    unsigned gen0 = *((volatile unsigned*)&gs.bar_gen);
    unsigned nb = 0;
    __syncthreads();

    // ---------------- recurrence ----------------
    for (int t = 0; t < Sz; t++) {
        // ===== Phase A: stage x, r; gates GEMM; LSTM =====
        for (int i = tid; i < 16 * Iz / 4; i += NT) {
            int b = i >> 6, c4 = (i & 63) << 2;
            *(float4*)&s->V[b * KVP + c4] =
                *(const float4*)&X[(((size_t)(b0 + b)) * Sz + t) * Iz + c4];
        }
        if (t > 0) {
            for (int i = tid; i < 16 * Cz / 4; i += NT) {
                int b = i >> 4, c4 = (i & 15) << 2;
                *(float4*)&s->V[b * KVP + Iz + c4] =
                    *(const float4*)&gs.r[(b0 + b) * Cz + c4];
            }
        }
        __syncthreads();
        {
            const int row = tid & 31, oct = (tid >> 5) & 1, kq = tid >> 6;
            const float* Wp = &s->WA[row * KVP + kq * 208];
            const float* Vp = &s->V[oct * 8 * KVP + kq * 208];
            float a0 = 0, a1 = 0, a2 = 0, a3 = 0, a4 = 0, a5 = 0, a6 = 0, a7 = 0;
            #pragma unroll 4
            for (int k = 0; k < 208; k += 4) {
                float4 w = *(const float4*)(Wp + k);
                float4 v;
                v = *(const float4*)(Vp + 0 * KVP + k);
                a0 = fmaf(w.x, v.x, a0); a0 = fmaf(w.y, v.y, a0); a0 = fmaf(w.z, v.z, a0); a0 = fmaf(w.w, v.w, a0);
                v = *(const float4*)(Vp + 1 * KVP + k);
                a1 = fmaf(w.x, v.x, a1); a1 = fmaf(w.y, v.y, a1); a1 = fmaf(w.z, v.z, a1); a1 = fmaf(w.w, v.w, a1);
                v = *(const float4*)(Vp + 2 * KVP + k);
                a2 = fmaf(w.x, v.x, a2); a2 = fmaf(w.y, v.y, a2); a2 = fmaf(w.z, v.z, a2); a2 = fmaf(w.w, v.w, a2);
                v = *(const float4*)(Vp + 3 * KVP + k);
                a3 = fmaf(w.x, v.x, a3); a3 = fmaf(w.y, v.y, a3); a3 = fmaf(w.z, v.z, a3); a3 = fmaf(w.w, v.w, a3);
                v = *(const float4*)(Vp + 4 * KVP + k);
                a4 = fmaf(w.x, v.x, a4); a4 = fmaf(w.y, v.y, a4); a4 = fmaf(w.z, v.z, a4); a4 = fmaf(w.w, v.w, a4);
                v = *(const float4*)(Vp + 5 * KVP + k);
                a5 = fmaf(w.x, v.x, a5); a5 = fmaf(w.y, v.y, a5); a5 = fmaf(w.z, v.z, a5); a5 = fmaf(w.w, v.w, a5);
                v = *(const float4*)(Vp + 6 * KVP + k);
                a6 = fmaf(w.x, v.x, a6); a6 = fmaf(w.y, v.y, a6); a6 = fmaf(w.z, v.z, a6); a6 = fmaf(w.w, v.w, a6);
                v = *(const float4*)(Vp + 7 * KVP + k);
                a7 = fmaf(w.x, v.x, a7); a7 = fmaf(w.y, v.y, a7); a7 = fmaf(w.z, v.z, a7); a7 = fmaf(w.w, v.w, a7);
            }
            // each thread owns exactly slots [oct*8 .. oct*8+7]
            float* gp = &s->gb4[(kq * 32 + row) * GBP + oct * 8];
            gp[0] = a0; gp[1] = a1; gp[2] = a2; gp[3] = a3;
            gp[4] = a4; gp[5] = a5; gp[6] = a6; gp[7] = a7;
        }
        __syncthreads();
        if (tid < 128) {
            int jj = tid >> 4, b = tid & 15;
            float G[4];
            #pragma unroll
            for (int g = 0; g < 4; g++) {
                int rr = g * 8 + jj;
                float acc = s->bA[rr];
                #pragma unroll
                for (int kq = 0; kq < 4; kq++) acc += s->gb4[(kq * 32 + rr) * GBP + b];
                G[g] = acc;
            }
            float c = sg_(G[1]) * s->cst[tid] + sg_(G[0]) * tanhf(G[2]);
            float h = sg_(G[3]) * tanhf(c);
            s->cst[tid] = c;
            gs.h[(b0 + b) * Hz + RG * 8 + jj] = h;
        }
        gbar(gen0, nb);

        // ===== Phase B: p = h@Whd^T, outh = h@Wout[:, :512]^T =====
        for (int i = tid; i < 16 * Hz / 4; i += NT) {
            int b = i >> 7, c4 = (i & 127) << 2;
            *(float4*)&s->V[b * KVP + 320 + c4] =
                *(const float4*)&gs.h[(b0 + b) * Hz + c4];
        }
        __syncthreads();
        if (tid < cnt * 16) {
            int rr = tid >> 4, b = tid & 15;
            const float* Wp = &s->WB[rr * WBP];
            const float* hp = &s->V[b * KVP + 320];
            float p0 = 0.f, p1 = 0.f;
            #pragma unroll 4
            for (int k = 0; k < Hz; k += 8) {
                float4 w = *(const float4*)(Wp + k);
                float4 v = *(const float4*)(hp + k);
                p0 = fmaf(w.x, v.x, p0); p0 = fmaf(w.y, v.y, p0);
                p0 = fmaf(w.z, v.z, p0); p0 = fmaf(w.w, v.w, p0);
                float4 w2 = *(const float4*)(Wp + k + 4);
                float4 v2 = *(const float4*)(hp + k + 4);
                p1 = fmaf(w2.x, v2.x, p1); p1 = fmaf(w2.y, v2.y, p1);
                p1 = fmaf(w2.z, v2.z, p1); p1 = fmaf(w2.w, v2.w, p1);
            }
            float acc = p0 + p1 + s->bB[rr];
            int gr = base + rr;
            if (gr < Pz) gs.p[(b0 + b) * Pz + gr] = acc;
            else         gs.outh[(b0 + b) * Oz + (gr - Pz)] = acc;
        }
        gbar(gen0, nb);

        // ===== Phase C: NTM addressing + memory (batch CTAs) =====
        if (bx < Bz) {
            for (int i = tid; i < Pz; i += NT) s->pb[i] = gs.p[bx * Pz + i];  // FIX: Pz=268 > NT
            __syncthreads();
            if (tid < 64) {
                s->kr[tid] = s->pb[tid];
                s->kw[tid] = s->pb[70 + tid];
                s->eb[tid] = sg_(s->pb[140 + tid]);
                s->ab[tid] = s->pb[204 + tid];
            }
            if (tid == 0) {
                #pragma unroll
                for (int hh = 0; hh < 2; hh++) {
                    int o = hh ? 70 : 0;
                    float kn = 0.f;
                    for (int c = 0; c < 64; c++) { float kv = s->pb[o + c]; kn = fmaf(kv, kv, kn); }
                    kn = sqrtf(kn);
                    float s0 = s->pb[o + 66], s1 = s->pb[o + 67], s2 = s->pb[o + 68];
                    float mx = fmaxf(s0, fmaxf(s1, s2));
                    float e0 = expf(s0 - mx), e1 = expf(s1 - mx), e2 = expf(s2 - mx);
                    float inv = 1.f / (e0 + e1 + e2);
                    float* c_ = &s->sc[hh * 8];
                    c_[0] = sp_(s->pb[o + 64]);
                    c_[1] = sg_(s->pb[o + 65]);
                    c_[2] = e0 * inv; c_[3] = e1 * inv; c_[4] = e2 * inv;
                    c_[5] = 1.f + sp_(s->pb[o + 69]);
                    c_[6] = 1.f / (kn + EPSF);
                }
            }
            __syncthreads();
            for (int hh = 0; hh < 2; hh++) {
                const float* kk = hh ? s->kw : s->kr;
                float* wprev = hh ? s->ww : s->wr;
                const float* c_ = &s->sc[hh * 8];
                float val = -1e30f;
                if (tid < 128) {
                    float d = 0.f;
                    const float* Mp = &s->M[tid * MP];
                    #pragma unroll
                    for (int c = 0; c < 64; c += 4) {
                        float4 m = *(const float4*)(Mp + c);
                        float4 k4 = *(const float4*)(kk + c);
                        d = fmaf(m.x, k4.x, d); d = fmaf(m.y, k4.y, d);
                        d = fmaf(m.z, k4.z, d); d = fmaf(m.w, k4.w, d);
                    }
                    val = c_[0] * d / (s->Mn[tid] + EPSF) * c_[6];
                }
                float mx = blk_max128(val, s, tid);
                float ex = (tid < 128) ? expf(val - mx) : 0.f;
                float sum = blk_sum128(ex, s, tid);
                if (tid < 128) {
                    float wc = ex / sum;
                    s->t1[tid] = c_[1] * wc + (1.f - c_[1]) * wprev[tid];
                }
                __syncthreads();
                float wp = 0.f;
                if (tid < 128) {
                    float ws = c_[2] * s->t1[(tid + 1) & 127]
                             + c_[3] * s->t1[tid]
                             + c_[4] * s->t1[(tid + 127) & 127];
                    wp = powf(ws + EPSF, c_[5]);
                }
                float sw = blk_sum128(wp, s, tid);
                if (tid < 128) wprev[tid] = wp / sw;
                __syncthreads();
            }
            if (tid < 128) {
                float wwn = s->ww[tid];
                float* Mp = &s->M[tid * MP];
                float nn = 0.f;
                #pragma unroll
                for (int c = 0; c < 64; c++) {
                    float m = Mp[c] * (1.f - wwn * s->eb[c]) + wwn * s->ab[c];
                    Mp[c] = m; nn = fmaf(m, m, nn);
                }
                s->Mn[tid] = sqrtf(nn);
            }
            __syncthreads();
            if (tid < 64) {
                float acc = 0.f;
                #pragma unroll 4
                for (int n = 0; n < 128; n++) acc = fmaf(s->wr[n], s->M[n * MP + tid], acc);
                gs.r[bx * Cz + tid] = acc;
            }
        }
        gbar(gen0, nb);

        // ===== Phase D: out = outh + r @ WoR^T =====
        for (int i = tid; i < Bz * Cz / 4; i += NT) {
            int b = i >> 4, c4 = (i & 15) << 2;
            float4 rv = *(const float4*)&gs.r[b * Cz + c4];
            s->gb4[(c4 + 0) * 32 + b] = rv.x;
            s->gb4[(c4 + 1) * 32 + b] = rv.y;
            s->gb4[(c4 + 2) * 32 + b] = rv.z;
            s->gb4[(c4 + 3) * 32 + b] = rv.w;
        }
        __syncthreads();
        if (tid < 64) {
            int oi = tid >> 5, b = tid & 31;
            int o = bx * 2 + oi;
            float acc = gs.outh[b * Oz + o];
            const float* wo = &s->WoR[oi * Cz];
            #pragma unroll 8
            for (int c = 0; c < 64; c++) acc = fmaf(s->gb4[c * 32 + b], wo[c], acc);
            Y[(((size_t)b) * Sz + t) * Oz + o] = acc;
        }
        // next-iteration staging __syncthreads orders gb4 reuse
    }
}

extern "C" void kernel_launch(void* const* d_in, const int* in_sizes, int n_in,
                              void* d_out, int out_size) {
    (void)in_sizes; (void)n_in; (void)out_size;
    const float* X    = (const float*)d_in[0];
    const float* Wih  = (const float*)d_in[1];
    const float* Whh  = (const float*)d_in[2];
    const float* bl   = (const float*)d_in[3];
    const float* Whd  = (const float*)d_in[4];
    const float* bhd  = (const float*)d_in[5];
    const float* Wout = (const float*)d_in[6];
    const float* bout = (const float*)d_in[7];
    float* Y = (float*)d_out;

    cudaFuncSetAttribute(ntm_kernel, cudaFuncAttributeMaxDynamicSharedMemorySize,
                         (int)sizeof(Smem));
    ntm_kernel<<<GRID, NT, sizeof(Smem)>>>(X, Wih, Whh, bl, Whd, bhd, Wout, bout, Y);
}

// round 9
// speedup vs baseline: 1.5364x; 1.5364x over previous
#include <cuda_runtime.h>
#include <math.h>

#define GRID 128
#define NT   256
#define Bz   32
#define Sz   256
#define Iz   256
#define Hz   512
#define Nz   128
#define Cz   64
#define Oz   256
#define Pz   268
#define KV   832
#define KVP  836
#define WBP  516
#define MP   68
#define GBP  17      // gb4 row pad
#define EPSF 1e-8f

struct GState {
    unsigned flags[GRID];   // per-CTA arrival epochs (monotone)
    unsigned release;       // barrier release epoch (monotone)
    unsigned pad[31];
    float h[Bz * Hz];
    float r[Bz * Cz];
    float p[Bz * Pz];
    float outh[Bz * Oz];
};
__device__ GState gs;

struct Smem {
    float WA[32 * KVP];      // gate weight rows [Wih|Whh], padded
    float V[16 * KVP];       // [x|r|h] for this CTA's 16 batches
    float WB[9 * WBP];       // head/out rows
    float gb4[4 * 32 * GBP]; // GEMM k-partials; reused as rbuf[c*32+b] in D
    float M[Nz * MP];
    float Mn[Nz];
    float wr[Nz];
    float ww[Nz];
    float t1[Nz];
    float pb[Pz];
    float kr[Cz]; float kw[Cz]; float eb[Cz]; float ab[Cz];
    float cst[8 * 16];
    float bA[32];
    float bB[9];
    float WoR[2 * Cz];
    float sc[16];
    float red[8];
};

extern __shared__ __align__(16) unsigned char smraw[];

__device__ __forceinline__ float sg_(float x) { return 1.f / (1.f + expf(-x)); }
__device__ __forceinline__ float sp_(float x) { return (x > 20.f) ? x : log1pf(expf(x)); }

// Distributed-flag grid barrier: per-CTA arrival slots (no atomic contention),
// CTA 0 aggregates with 128 parallel pollers, single release word.
__device__ __forceinline__ void gbar(unsigned gen0, unsigned &nb, int tid, int bx) {
    nb++;
    const unsigned target = gen0 + nb;
    __syncthreads();
    if (tid == 0) {
        __threadfence();
        atomicExch(&gs.flags[bx], target);
    }
    if (bx == 0) {
        if (tid < GRID) {
            volatile unsigned* f = &gs.flags[tid];
            while ((int)(*f - target) < 0) {}
        }
        __syncthreads();
        if (tid == 0) {
            __threadfence();
            atomicExch(&gs.release, target);
        }
    }
    if (tid == 0) {
        volatile unsigned* rel = &gs.release;
        while ((int)(*rel - target) < 0) {}
        __threadfence();
    }
    __syncthreads();
}

__device__ __forceinline__ float blk_max128(float v, Smem* s, int tid) {
    #pragma unroll
    for (int o = 16; o > 0; o >>= 1) v = fmaxf(v, __shfl_xor_sync(0xffffffffu, v, o));
    if (tid < 128 && (tid & 31) == 0) s->red[tid >> 5] = v;
    __syncthreads();
    float m = fmaxf(fmaxf(s->red[0], s->red[1]), fmaxf(s->red[2], s->red[3]));
    __syncthreads();
    return m;
}
__device__ __forceinline__ float blk_sum128(float v, Smem* s, int tid) {
    #pragma unroll
    for (int o = 16; o > 0; o >>= 1) v += __shfl_xor_sync(0xffffffffu, v, o);
    if (tid < 128 && (tid & 31) == 0) s->red[tid >> 5] = v;
    __syncthreads();
    float m = s->red[0] + s->red[1] + s->red[2] + s->red[3];
    __syncthreads();
    return m;
}

__global__ void __launch_bounds__(NT, 1)
ntm_kernel(const float* __restrict__ X,
           const float* __restrict__ Wih, const float* __restrict__ Whh,
           const float* __restrict__ bl,
           const float* __restrict__ Whd, const float* __restrict__ bhd,
           const float* __restrict__ Wout, const float* __restrict__ bout,
           float* __restrict__ Y)
{
    Smem* s = (Smem*)smraw;
    const int tid = threadIdx.x, bx = blockIdx.x;
    const int RG = bx >> 1, BH = bx & 1, b0 = BH * 16;

    // ---------------- one-time staging ----------------
    for (int rr = 0; rr < 32; rr++) {
        int gr = (rr >> 3) * Hz + RG * 8 + (rr & 7);
        for (int k = tid; k < KV; k += NT)
            s->WA[rr * KVP + k] = (k < 320) ? Wih[gr * 320 + k] : Whh[gr * Hz + (k - 320)];
    }
    if (tid < 32) {
        int gr = (tid >> 3) * Hz + RG * 8 + (tid & 7);
        s->bA[tid] = bl[gr];
    }
    const int base = RG * 9;
    const int cnt = (base >= 524) ? 0 : ((524 - base < 9) ? (524 - base) : 9);
    for (int rr = 0; rr < cnt; rr++) {
        int gr = base + rr;
        for (int k = tid; k < Hz; k += NT)
            s->WB[rr * WBP + k] = (gr < Pz) ? Whd[gr * Hz + k] : Wout[(gr - Pz) * 576 + k];
    }
    if (tid < cnt) {
        int gr = base + tid;
        s->bB[tid] = (gr < Pz) ? bhd[gr] : bout[gr - Pz];
    }
    for (int i = tid; i < 2 * Cz; i += NT)
        s->WoR[i] = Wout[(bx * 2 + (i >> 6)) * 576 + 512 + (i & 63)];
    for (int i = tid; i < 16 * KVP; i += NT) s->V[i] = 0.f;
    if (tid < 128) s->cst[tid] = 0.f;
    if (bx < Bz) {
        for (int i = tid; i < Nz * Cz; i += NT) s->M[(i >> 6) * MP + (i & 63)] = 0.01f;
        if (tid < Nz) {
            float w0 = (tid == 0) ? 1.f : 0.f;
            s->wr[tid] = w0; s->ww[tid] = w0; s->Mn[tid] = 0.08f;
        }
    }
    unsigned gen0 = *((volatile unsigned*)&gs.release);
    unsigned nb = 0;
    __syncthreads();

    // ---------------- recurrence ----------------
    for (int t = 0; t < Sz; t++) {
        // ===== Phase A: stage x, r; gates GEMM; LSTM =====
        for (int i = tid; i < 16 * Iz / 4; i += NT) {
            int b = i >> 6, c4 = (i & 63) << 2;
            *(float4*)&s->V[b * KVP + c4] =
                *(const float4*)&X[(((size_t)(b0 + b)) * Sz + t) * Iz + c4];
        }
        if (t > 0) {
            for (int i = tid; i < 16 * Cz / 4; i += NT) {
                int b = i >> 4, c4 = (i & 15) << 2;
                *(float4*)&s->V[b * KVP + Iz + c4] =
                    *(const float4*)&gs.r[(b0 + b) * Cz + c4];
            }
        }
        __syncthreads();
        // GEMM on 128 threads: kq = warp (4), rowg 16 (rows rowg & rowg+16), oct 2.
        // Each W/V element is read exactly once per CTA (intra-warp broadcast dedup).
        if (tid < 128) {
            const int oct = tid & 1, rowg = (tid >> 1) & 15, kq = tid >> 5;
            const float* Wp0 = &s->WA[rowg * KVP + kq * 208];
            const float* Wp1 = &s->WA[(rowg + 16) * KVP + kq * 208];
            const float* Vp  = &s->V[oct * 8 * KVP + kq * 208];
            float ac0[8], ac1[8];
            #pragma unroll
            for (int j = 0; j < 8; j++) { ac0[j] = 0.f; ac1[j] = 0.f; }
            #pragma unroll 2
            for (int k = 0; k < 208; k += 4) {
                float4 w0 = *(const float4*)(Wp0 + k);
                float4 w1 = *(const float4*)(Wp1 + k);
                #pragma unroll
                for (int j = 0; j < 8; j++) {
                    float4 v = *(const float4*)(Vp + j * KVP + k);
                    ac0[j] = fmaf(w0.x, v.x, ac0[j]); ac0[j] = fmaf(w0.y, v.y, ac0[j]);
                    ac0[j] = fmaf(w0.z, v.z, ac0[j]); ac0[j] = fmaf(w0.w, v.w, ac0[j]);
                    ac1[j] = fmaf(w1.x, v.x, ac1[j]); ac1[j] = fmaf(w1.y, v.y, ac1[j]);
                    ac1[j] = fmaf(w1.z, v.z, ac1[j]); ac1[j] = fmaf(w1.w, v.w, ac1[j]);
                }
            }
            float* g0 = &s->gb4[(kq * 32 + rowg) * GBP + oct * 8];
            float* g1 = &s->gb4[(kq * 32 + rowg + 16) * GBP + oct * 8];
            #pragma unroll
            for (int j = 0; j < 8; j++) { g0[j] = ac0[j]; g1[j] = ac1[j]; }
        }
        __syncthreads();
        if (tid < 128) {
            int jj = tid >> 4, b = tid & 15;
            float G[4];
            #pragma unroll
            for (int g = 0; g < 4; g++) {
                int rr = g * 8 + jj;
                float acc = s->bA[rr];
                #pragma unroll
                for (int kq = 0; kq < 4; kq++) acc += s->gb4[(kq * 32 + rr) * GBP + b];
                G[g] = acc;
            }
            float c = sg_(G[1]) * s->cst[tid] + sg_(G[0]) * tanhf(G[2]);
            float h = sg_(G[3]) * tanhf(c);
            s->cst[tid] = c;
            gs.h[(b0 + b) * Hz + RG * 8 + jj] = h;
        }
        gbar(gen0, nb, tid, bx);

        // ===== Phase B: p = h@Whd^T, outh = h@Wout[:, :512]^T =====
        for (int i = tid; i < 16 * Hz / 4; i += NT) {
            int b = i >> 7, c4 = (i & 127) << 2;
            *(float4*)&s->V[b * KVP + 320 + c4] =
                *(const float4*)&gs.h[(b0 + b) * Hz + c4];
        }
        __syncthreads();
        if (tid < cnt * 16) {
            int rr = tid >> 4, b = tid & 15;
            const float* Wp = &s->WB[rr * WBP];
            const float* hp = &s->V[b * KVP + 320];
            float q0 = 0.f, q1 = 0.f, q2 = 0.f, q3 = 0.f;
            #pragma unroll 2
            for (int k = 0; k < Hz; k += 16) {
                float4 w, v;
                w = *(const float4*)(Wp + k);      v = *(const float4*)(hp + k);
                q0 = fmaf(w.x, v.x, q0); q0 = fmaf(w.y, v.y, q0);
                q0 = fmaf(w.z, v.z, q0); q0 = fmaf(w.w, v.w, q0);
                w = *(const float4*)(Wp + k + 4);  v = *(const float4*)(hp + k + 4);
                q1 = fmaf(w.x, v.x, q1); q1 = fmaf(w.y, v.y, q1);
                q1 = fmaf(w.z, v.z, q1); q1 = fmaf(w.w, v.w, q1);
                w = *(const float4*)(Wp + k + 8);  v = *(const float4*)(hp + k + 8);
                q2 = fmaf(w.x, v.x, q2); q2 = fmaf(w.y, v.y, q2);
                q2 = fmaf(w.z, v.z, q2); q2 = fmaf(w.w, v.w, q2);
                w = *(const float4*)(Wp + k + 12); v = *(const float4*)(hp + k + 12);
                q3 = fmaf(w.x, v.x, q3); q3 = fmaf(w.y, v.y, q3);
                q3 = fmaf(w.z, v.z, q3); q3 = fmaf(w.w, v.w, q3);
            }
            float acc = (q0 + q1) + (q2 + q3) + s->bB[rr];
            int gr = base + rr;
            if (gr < Pz) gs.p[(b0 + b) * Pz + gr] = acc;
            else         gs.outh[(b0 + b) * Oz + (gr - Pz)] = acc;
        }
        gbar(gen0, nb, tid, bx);

        // ===== Phase C: NTM addressing + memory (batch CTAs) =====
        if (bx < Bz) {
            for (int i = tid; i < Pz; i += NT) s->pb[i] = gs.p[bx * Pz + i];
            __syncthreads();
            if (tid < 64) {
                s->kr[tid] = s->pb[tid];
                s->kw[tid] = s->pb[70 + tid];
                s->eb[tid] = sg_(s->pb[140 + tid]);
                s->ab[tid] = s->pb[204 + tid];
            }
            if (tid == 0) {
                #pragma unroll
                for (int hh = 0; hh < 2; hh++) {
                    int o = hh ? 70 : 0;
                    float kn = 0.f;
                    for (int c = 0; c < 64; c++) { float kv = s->pb[o + c]; kn = fmaf(kv, kv, kn); }
                    kn = sqrtf(kn);
                    float s0 = s->pb[o + 66], s1 = s->pb[o + 67], s2 = s->pb[o + 68];
                    float mx = fmaxf(s0, fmaxf(s1, s2));
                    float e0 = expf(s0 - mx), e1 = expf(s1 - mx), e2 = expf(s2 - mx);
                    float inv = 1.f / (e0 + e1 + e2);
                    float* c_ = &s->sc[hh * 8];
                    c_[0] = sp_(s->pb[o + 64]);
                    c_[1] = sg_(s->pb[o + 65]);
                    c_[2] = e0 * inv; c_[3] = e1 * inv; c_[4] = e2 * inv;
                    c_[5] = 1.f + sp_(s->pb[o + 69]);
                    c_[6] = 1.f / (kn + EPSF);
                }
            }
            __syncthreads();
            for (int hh = 0; hh < 2; hh++) {
                const float* kk = hh ? s->kw : s->kr;
                float* wprev = hh ? s->ww : s->wr;
                const float* c_ = &s->sc[hh * 8];
                float val = -1e30f;
                if (tid < 128) {
                    float d = 0.f;
                    const float* Mp = &s->M[tid * MP];
                    #pragma unroll
                    for (int c = 0; c < 64; c += 4) {
                        float4 m = *(const float4*)(Mp + c);
                        float4 k4 = *(const float4*)(kk + c);
                        d = fmaf(m.x, k4.x, d); d = fmaf(m.y, k4.y, d);
                        d = fmaf(m.z, k4.z, d); d = fmaf(m.w, k4.w, d);
                    }
                    val = c_[0] * d / (s->Mn[tid] + EPSF) * c_[6];
                }
                float mx = blk_max128(val, s, tid);
                float ex = (tid < 128) ? expf(val - mx) : 0.f;
                float sum = blk_sum128(ex, s, tid);
                if (tid < 128) {
                    float wc = ex / sum;
                    s->t1[tid] = c_[1] * wc + (1.f - c_[1]) * wprev[tid];
                }
                __syncthreads();
                float wp = 0.f;
                if (tid < 128) {
                    float ws = c_[2] * s->t1[(tid + 1) & 127]
                             + c_[3] * s->t1[tid]
                             + c_[4] * s->t1[(tid + 127) & 127];
                    wp = powf(ws + EPSF, c_[5]);
                }
                float sw = blk_sum128(wp, s, tid);
                if (tid < 128) wprev[tid] = wp / sw;
                __syncthreads();
            }
            if (tid < 128) {
                float wwn = s->ww[tid];
                float* Mp = &s->M[tid * MP];
                float nn = 0.f;
                #pragma unroll
                for (int c = 0; c < 64; c++) {
                    float m = Mp[c] * (1.f - wwn * s->eb[c]) + wwn * s->ab[c];
                    Mp[c] = m; nn = fmaf(m, m, nn);
                }
                s->Mn[tid] = sqrtf(nn);
            }
            __syncthreads();
            if (tid < 64) {
                float acc = 0.f;
                #pragma unroll 4
                for (int n = 0; n < 128; n++) acc = fmaf(s->wr[n], s->M[n * MP + tid], acc);
                gs.r[bx * Cz + tid] = acc;
            }
        }
        gbar(gen0, nb, tid, bx);

        // ===== Phase D: out = outh + r @ WoR^T =====
        for (int i = tid; i < Bz * Cz / 4; i += NT) {
            int b = i >> 4, c4 = (i & 15) << 2;
            float4 rv = *(const float4*)&gs.r[b * Cz + c4];
            s->gb4[(c4 + 0) * 32 + b] = rv.x;
            s->gb4[(c4 + 1) * 32 + b] = rv.y;
            s->gb4[(c4 + 2) * 32 + b] = rv.z;
            s->gb4[(c4 + 3) * 32 + b] = rv.w;
        }
        __syncthreads();
        if (tid < 64) {
            int oi = tid >> 5, b = tid & 31;
            int o = bx * 2 + oi;
            float acc = gs.outh[b * Oz + o];
            const float* wo = &s->WoR[oi * Cz];
            #pragma unroll 8
            for (int c = 0; c < 64; c++) acc = fmaf(s->gb4[c * 32 + b], wo[c], acc);
            Y[(((size_t)b) * Sz + t) * Oz + o] = acc;
        }
        // next-iteration staging __syncthreads orders gb4 reuse
    }
}

extern "C" void kernel_launch(void* const* d_in, const int* in_sizes, int n_in,
                              void* d_out, int out_size) {
    (void)in_sizes; (void)n_in; (void)out_size;
    const float* X    = (const float*)d_in[0];
    const float* Wih  = (const float*)d_in[1];
    const float* Whh  = (const float*)d_in[2];
    const float* bl   = (const float*)d_in[3];
    const float* Whd  = (const float*)d_in[4];
    const float* bhd  = (const float*)d_in[5];
    const float* Wout = (const float*)d_in[6];
    const float* bout = (const float*)d_in[7];
    float* Y = (float*)d_out;

    cudaFuncSetAttribute(ntm_kernel, cudaFuncAttributeMaxDynamicSharedMemorySize,
                         (int)sizeof(Smem));
    ntm_kernel<<<GRID, NT, sizeof(Smem)>>>(X, Wih, Whh, bl, Whd, bhd, Wout, bout, Y);
}

// round 10
// speedup vs baseline: 1.7671x; 1.1501x over previous
#include <cuda_runtime.h>
#include <math.h>

#define GRID 128
#define NT   256
#define Bz   32
#define Sz   256
#define Iz   256
#define Hz   512
#define Nz   128
#define Cz   64
#define Oz   256
#define Pz   268
#define KV   832
#define KVP  836
#define WBP  516
#define MP   68
#define GBP  17      // gb4 row pad
#define EPSF 1e-8f

struct GState {
    unsigned flags[GRID];   // per-CTA arrival epochs (monotone)
    unsigned pad[32];
    float h[Bz * Hz];
    float r[Bz * Cz];
    float p[Bz * Pz];
    float outh[Bz * Oz];
};
__device__ GState gs;

struct Smem {
    float WA[32 * KVP];      // gate weight rows [Wih|Whh], padded
    float V[16 * KVP];       // [x|r|h] for this CTA's 16 batches
    float WB[9 * WBP];       // head/out rows
    float gb4[4 * 32 * GBP]; // GEMM k-partials; reused as rbuf[c*32+b] in D
    float M[Nz * MP];
    float Mn[Nz];
    float wr[Nz];
    float ww[Nz];
    float t1[2 * Nz];        // per-head shift buffers / r partials
    float pb[Pz];
    float kr[Cz]; float kw[Cz]; float eb[Cz]; float ab[Cz];
    float cst[8 * 16];
    float bA[32];
    float bB[9];
    float WoR[3 * Cz];       // D rows for CTAs >= 32 (3 rows each)
    float sc[16];
    float red[8];
};

extern __shared__ __align__(16) unsigned char smraw[];

__device__ __forceinline__ float sg_(float x) { return 1.f / (1.f + expf(-x)); }
__device__ __forceinline__ float sp_(float x) { return (x > 20.f) ? x : log1pf(expf(x)); }

// packed fp32 FMA (Blackwell FFMA2): 2 MACs per instruction
__device__ __forceinline__ unsigned long long ffma2_(unsigned long long a,
                                                     unsigned long long b,
                                                     unsigned long long c) {
    unsigned long long d;
    asm("fma.rn.f32x2 %0, %1, %2, %3;" : "=l"(d) : "l"(a), "l"(b), "l"(c));
    return d;
}
__device__ __forceinline__ float hsum2_(unsigned long long v) {
    float lo, hi;
    asm("mov.b64 {%0, %1}, %2;" : "=f"(lo), "=f"(hi) : "l"(v));
    return lo + hi;
}

// Symmetric distributed-flag grid barrier: every CTA publishes its epoch,
// every CTA's first 128 threads poll all flags (one coalesced line per warp).
__device__ __forceinline__ void gbar(unsigned gen0, unsigned &nb, int tid, int bx) {
    nb++;
    const unsigned target = gen0 + nb;
    __syncthreads();
    if (tid == 0) {
        __threadfence();
        atomicExch(&gs.flags[bx], target);
    }
    if (tid < GRID) {
        volatile unsigned* f = &gs.flags[tid];
        while ((int)(*f - target) < 0) {}
    }
    __threadfence();
    __syncthreads();
}

// 128-thread-group reductions (group = tid>>7), both groups call together
__device__ __forceinline__ float grp_max128(float v, Smem* s, int tid) {
    #pragma unroll
    for (int o = 16; o > 0; o >>= 1) v = fmaxf(v, __shfl_xor_sync(0xffffffffu, v, o));
    int g4 = (tid >> 7) * 4;
    if ((tid & 31) == 0) s->red[g4 + ((tid >> 5) & 3)] = v;
    __syncthreads();
    float m = fmaxf(fmaxf(s->red[g4 + 0], s->red[g4 + 1]),
                    fmaxf(s->red[g4 + 2], s->red[g4 + 3]));
    __syncthreads();
    return m;
}
__device__ __forceinline__ float grp_sum128(float v, Smem* s, int tid) {
    #pragma unroll
    for (int o = 16; o > 0; o >>= 1) v += __shfl_xor_sync(0xffffffffu, v, o);
    int g4 = (tid >> 7) * 4;
    if ((tid & 31) == 0) s->red[g4 + ((tid >> 5) & 3)] = v;
    __syncthreads();
    float m = (s->red[g4 + 0] + s->red[g4 + 1]) + (s->red[g4 + 2] + s->red[g4 + 3]);
    __syncthreads();
    return m;
}

__global__ void __launch_bounds__(NT, 1)
ntm_kernel(const float* __restrict__ X,
           const float* __restrict__ Wih, const float* __restrict__ Whh,
           const float* __restrict__ bl,
           const float* __restrict__ Whd, const float* __restrict__ bhd,
           const float* __restrict__ Wout, const float* __restrict__ bout,
           float* __restrict__ Y)
{
    Smem* s = (Smem*)smraw;
    const int tid = threadIdx.x, bx = blockIdx.x;
    const int RG = bx >> 1, BH = bx & 1, b0 = BH * 16;

    // ---------------- one-time staging ----------------
    for (int rr = 0; rr < 32; rr++) {
        int gr = (rr >> 3) * Hz + RG * 8 + (rr & 7);
        for (int k = tid; k < KV; k += NT)
            s->WA[rr * KVP + k] = (k < 320) ? Wih[gr * 320 + k] : Whh[gr * Hz + (k - 320)];
    }
    if (tid < 32) {
        int gr = (tid >> 3) * Hz + RG * 8 + (tid & 7);
        s->bA[tid] = bl[gr];
    }
    const int base = RG * 9;
    const int cnt = (base >= 524) ? 0 : ((524 - base < 9) ? (524 - base) : 9);
    for (int rr = 0; rr < cnt; rr++) {
        int gr = base + rr;
        for (int k = tid; k < Hz; k += NT)
            s->WB[rr * WBP + k] = (gr < Pz) ? Whd[gr * Hz + k] : Wout[(gr - Pz) * 576 + k];
    }
    if (tid < cnt) {
        int gr = base + tid;
        s->bB[tid] = (gr < Pz) ? bhd[gr] : bout[gr - Pz];
    }
    // D-row weights: CTAs 32..127 own up to 3 output rows each
    if (bx >= Bz) {
        for (int i = tid; i < 3 * Cz; i += NT) {
            int o = (bx - Bz) * 3 + (i >> 6);
            if (o < Oz) s->WoR[i] = Wout[o * 576 + 512 + (i & 63)];
        }
    }
    for (int i = tid; i < 16 * KVP; i += NT) s->V[i] = 0.f;
    if (tid < 128) s->cst[tid] = 0.f;
    if (bx < Bz) {
        for (int i = tid; i < Nz * Cz; i += NT) s->M[(i >> 6) * MP + (i & 63)] = 0.01f;
        if (tid < Nz) {
            float w0 = (tid == 0) ? 1.f : 0.f;
            s->wr[tid] = w0; s->ww[tid] = w0; s->Mn[tid] = 0.08f;
        }
    }
    unsigned gen0 = *((volatile unsigned*)&gs.flags[bx]);
    unsigned nb = 0;
    __syncthreads();

    // ---------------- recurrence ----------------
    for (int t = 0; t < Sz; t++) {
        // ===== Phase A: stage x, r; gates GEMM (FFMA2); LSTM =====
        for (int i = tid; i < 16 * Iz / 4; i += NT) {
            int b = i >> 6, c4 = (i & 63) << 2;
            *(float4*)&s->V[b * KVP + c4] =
                *(const float4*)&X[(((size_t)(b0 + b)) * Sz + t) * Iz + c4];
        }
        if (t > 0) {
            for (int i = tid; i < 16 * Cz / 4; i += NT) {
                int b = i >> 4, c4 = (i & 15) << 2;
                *(float4*)&s->V[b * KVP + Iz + c4] =
                    *(const float4*)&gs.r[(b0 + b) * Cz + c4];
            }
        }
        __syncthreads();
        if (tid < 128) {
            const int oct = tid & 1, rowg = (tid >> 1) & 15, kq = tid >> 5;
            const ulonglong2* W0 = (const ulonglong2*)&s->WA[rowg * KVP + kq * 208];
            const ulonglong2* W1 = (const ulonglong2*)&s->WA[(rowg + 16) * KVP + kq * 208];
            const float* Vbase = &s->V[oct * 8 * KVP + kq * 208];
            unsigned long long ac0[8], ac1[8];
            #pragma unroll
            for (int j = 0; j < 8; j++) { ac0[j] = 0ull; ac1[j] = 0ull; }
            #pragma unroll 2
            for (int i = 0; i < 52; i++) {
                ulonglong2 w0 = W0[i];
                ulonglong2 w1 = W1[i];
                #pragma unroll
                for (int j = 0; j < 8; j++) {
                    ulonglong2 v = *(const ulonglong2*)(Vbase + j * KVP + i * 4);
                    ac0[j] = ffma2_(w0.x, v.x, ac0[j]);
                    ac0[j] = ffma2_(w0.y, v.y, ac0[j]);
                    ac1[j] = ffma2_(w1.x, v.x, ac1[j]);
                    ac1[j] = ffma2_(w1.y, v.y, ac1[j]);
                }
            }
            float* g0 = &s->gb4[(kq * 32 + rowg) * GBP + oct * 8];
            float* g1 = &s->gb4[(kq * 32 + rowg + 16) * GBP + oct * 8];
            #pragma unroll
            for (int j = 0; j < 8; j++) { g0[j] = hsum2_(ac0[j]); g1[j] = hsum2_(ac1[j]); }
        }
        __syncthreads();
        if (tid < 128) {
            int jj = tid >> 4, b = tid & 15;
            float G[4];
            #pragma unroll
            for (int g = 0; g < 4; g++) {
                int rr = g * 8 + jj;
                float acc = s->bA[rr];
                #pragma unroll
                for (int kq = 0; kq < 4; kq++) acc += s->gb4[(kq * 32 + rr) * GBP + b];
                G[g] = acc;
            }
            float c = sg_(G[1]) * s->cst[tid] + sg_(G[0]) * tanhf(G[2]);
            float h = sg_(G[3]) * tanhf(c);
            s->cst[tid] = c;
            gs.h[(b0 + b) * Hz + RG * 8 + jj] = h;
        }
        gbar(gen0, nb, tid, bx);

        // ===== Phase B: p = h@Whd^T, outh = h@Wout[:, :512]^T (FFMA2) =====
        for (int i = tid; i < 16 * Hz / 4; i += NT) {
            int b = i >> 7, c4 = (i & 127) << 2;
            *(float4*)&s->V[b * KVP + 320 + c4] =
                *(const float4*)&gs.h[(b0 + b) * Hz + c4];
        }
        __syncthreads();
        if (tid < cnt * 16) {
            int rr = tid >> 4, b = tid & 15;
            const ulonglong2* Wp = (const ulonglong2*)&s->WB[rr * WBP];
            const ulonglong2* hp = (const ulonglong2*)&s->V[b * KVP + 320];
            unsigned long long q0 = 0ull, q1 = 0ull, q2 = 0ull, q3 = 0ull;
            #pragma unroll 4
            for (int i = 0; i < 128; i += 2) {
                ulonglong2 w = Wp[i], v = hp[i];
                q0 = ffma2_(w.x, v.x, q0);
                q1 = ffma2_(w.y, v.y, q1);
                w = Wp[i + 1]; v = hp[i + 1];
                q2 = ffma2_(w.x, v.x, q2);
                q3 = ffma2_(w.y, v.y, q3);
            }
            float acc = (hsum2_(q0) + hsum2_(q1)) + (hsum2_(q2) + hsum2_(q3)) + s->bB[rr];
            int gr = base + rr;
            if (gr < Pz) gs.p[(b0 + b) * Pz + gr] = acc;
            else         gs.outh[(b0 + b) * Oz + (gr - Pz)] = acc;
        }
        gbar(gen0, nb, tid, bx);

        // ===== Phase C: NTM addressing + memory — both heads in parallel =====
        if (bx < Bz) {
            for (int i = tid; i < Pz; i += NT) s->pb[i] = gs.p[bx * Pz + i];
            __syncthreads();
            if (tid < 64) {
                s->kr[tid] = s->pb[tid];
                s->kw[tid] = s->pb[70 + tid];
                s->eb[tid] = sg_(s->pb[140 + tid]);
                s->ab[tid] = s->pb[204 + tid];
            }
            if ((tid & 127) == 0) {
                int hh = tid >> 7;
                int o = hh ? 70 : 0;
                float kn = 0.f;
                for (int c = 0; c < 64; c++) { float kv = s->pb[o + c]; kn = fmaf(kv, kv, kn); }
                kn = sqrtf(kn);
                float s0 = s->pb[o + 66], s1 = s->pb[o + 67], s2 = s->pb[o + 68];
                float mx = fmaxf(s0, fmaxf(s1, s2));
                float e0 = expf(s0 - mx), e1 = expf(s1 - mx), e2 = expf(s2 - mx);
                float inv = 1.f / (e0 + e1 + e2);
                float* c_ = &s->sc[hh * 8];
                c_[0] = sp_(s->pb[o + 64]);
                c_[1] = sg_(s->pb[o + 65]);
                c_[2] = e0 * inv; c_[3] = e1 * inv; c_[4] = e2 * inv;
                c_[5] = 1.f + sp_(s->pb[o + 69]);
                c_[6] = 1.f / (kn + EPSF);
            }
            __syncthreads();
            {
                const int hh = tid >> 7, n = tid & 127;
                const float* kk = hh ? s->kw : s->kr;
                float* wprev = hh ? s->ww : s->wr;
                const float* c_ = &s->sc[hh * 8];
                float* t1h = &s->t1[hh * Nz];
                float d = 0.f;
                const float* Mp = &s->M[n * MP];
                #pragma unroll
                for (int c = 0; c < 64; c += 4) {
                    float4 m = *(const float4*)(Mp + c);
                    float4 k4 = *(const float4*)(kk + c);
                    d = fmaf(m.x, k4.x, d); d = fmaf(m.y, k4.y, d);
                    d = fmaf(m.z, k4.z, d); d = fmaf(m.w, k4.w, d);
                }
                float val = c_[0] * d / (s->Mn[n] + EPSF) * c_[6];
                float mx = grp_max128(val, s, tid);
                float ex = expf(val - mx);
                float sum = grp_sum128(ex, s, tid);
                float wc = ex / sum;
                t1h[n] = c_[1] * wc + (1.f - c_[1]) * wprev[n];
                __syncthreads();
                float ws = c_[2] * t1h[(n + 1) & 127]
                         + c_[3] * t1h[n]
                         + c_[4] * t1h[(n + 127) & 127];
                float wp = powf(ws + EPSF, c_[5]);
                float sw = grp_sum128(wp, s, tid);
                wprev[n] = wp / sw;
            }
            __syncthreads();
            if (tid < 128) {
                float wwn = s->ww[tid];
                float* Mp = &s->M[tid * MP];
                float nn = 0.f;
                #pragma unroll
                for (int c = 0; c < 64; c++) {
                    float m = Mp[c] * (1.f - wwn * s->eb[c]) + wwn * s->ab[c];
                    Mp[c] = m; nn = fmaf(m, m, nn);
                }
                s->Mn[tid] = sqrtf(nn);
            }
            __syncthreads();
            if (tid < 128) {
                int c = tid & 63, half = tid >> 6;
                int n0 = half * 64;
                float acc = 0.f;
                #pragma unroll 4
                for (int n2 = 0; n2 < 64; n2++)
                    acc = fmaf(s->wr[n0 + n2], s->M[(n0 + n2) * MP + c], acc);
                s->t1[tid] = acc;
            }
            __syncthreads();
            if (tid < 64) gs.r[bx * Cz + tid] = s->t1[tid] + s->t1[64 + tid];
        }
        gbar(gen0, nb, tid, bx);

        // ===== Phase D (CTAs 32..127 only): out = outh + r @ WoR^T =====
        if (bx >= Bz) {
            for (int i = tid; i < Bz * Cz / 4; i += NT) {
                int b = i >> 4, c4 = (i & 15) << 2;
                float4 rv = *(const float4*)&gs.r[b * Cz + c4];
                s->gb4[(c4 + 0) * 32 + b] = rv.x;
                s->gb4[(c4 + 1) * 32 + b] = rv.y;
                s->gb4[(c4 + 2) * 32 + b] = rv.z;
                s->gb4[(c4 + 3) * 32 + b] = rv.w;
            }
            __syncthreads();
            if (tid < 96) {
                int oi = tid >> 5, b = tid & 31;
                int o = (bx - Bz) * 3 + oi;
                if (o < Oz) {
                    float acc = gs.outh[b * Oz + o];
                    const float* wo = &s->WoR[oi * Cz];
                    #pragma unroll 8
                    for (int c = 0; c < 64; c++) acc = fmaf(s->gb4[c * 32 + b], wo[c], acc);
                    Y[(((size_t)b) * Sz + t) * Oz + o] = acc;
                }
            }
        }
        // next-iteration staging __syncthreads orders gb4 reuse
    }
}

extern "C" void kernel_launch(void* const* d_in, const int* in_sizes, int n_in,
                              void* d_out, int out_size) {
    (void)in_sizes; (void)n_in; (void)out_size;
    const float* X    = (const float*)d_in[0];
    const float* Wih  = (const float*)d_in[1];
    const float* Whh  = (const float*)d_in[2];
    const float* bl   = (const float*)d_in[3];
    const float* Whd  = (const float*)d_in[4];
    const float* bhd  = (const float*)d_in[5];
    const float* Wout = (const float*)d_in[6];
    const float* bout = (const float*)d_in[7];
    float* Y = (float*)d_out;

    cudaFuncSetAttribute(ntm_kernel, cudaFuncAttributeMaxDynamicSharedMemorySize,
                         (int)sizeof(Smem));
    ntm_kernel<<<GRID, NT, sizeof(Smem)>>>(X, Wih, Whh, bl, Whd, bhd, Wout, bout, Y);
}

// round 12
// speedup vs baseline: 2.0331x; 1.1506x over previous
#include <cuda_runtime.h>
#include <math.h>

#define GRID 128
#define NT   256
#define Bz   32
#define Sz   256
#define Iz   256
#define Hz   512
#define Nz   128
#define Cz   64
#define Oz   256
#define Pz   268
#define KV   832
#define KVP  836
#define WBP  516
#define MP   68
#define GBP  17
#define EPSF 1e-8f
#define SMEM_BYTES 226640

struct GState {
    unsigned flags[GRID];
    unsigned pad[32];
    float h[Bz * Hz];
    float r[Bz * Cz];
    float p[Bz * Pz];
    float outh[Bz * Oz];
};
__device__ GState gs;

extern __shared__ __align__(16) float sm[];

__device__ __forceinline__ float sg_(float x) { return 1.f / (1.f + expf(-x)); }
__device__ __forceinline__ float sp_(float x) { return (x > 20.f) ? x : log1pf(expf(x)); }

__device__ __forceinline__ unsigned long long ffma2_(unsigned long long a,
                                                     unsigned long long b,
                                                     unsigned long long c) {
    unsigned long long d;
    asm("fma.rn.f32x2 %0, %1, %2, %3;" : "=l"(d) : "l"(a), "l"(b), "l"(c));
    return d;
}
__device__ __forceinline__ float hsum2_(unsigned long long v) {
    float lo, hi;
    asm("mov.b64 {%0, %1}, %2;" : "=f"(lo), "=f"(hi) : "l"(v));
    return lo + hi;
}
// V row base with bank skew: batches 8..15 offset +4 words (oct conflict-free)
__device__ __forceinline__ int voffb(int b) { return b * KVP + ((b >= 8) ? 4 : 0); }

__device__ __forceinline__ void gbar(unsigned gen0, unsigned &nb, int tid, int bx) {
    nb++;
    const unsigned target = gen0 + nb;
    __syncthreads();
    if (tid == 0) { __threadfence(); atomicExch(&gs.flags[bx], target); }
    if (tid < GRID) {
        volatile unsigned* f = &gs.flags[tid];
        while ((int)(*f - target) < 0) {}
    }
    __threadfence();
    __syncthreads();
}

__device__ __forceinline__ float grp_max128(float v, float* red, int tid) {
    #pragma unroll
    for (int o = 16; o > 0; o >>= 1) v = fmaxf(v, __shfl_xor_sync(0xffffffffu, v, o));
    int g4 = (tid >> 7) * 4;
    if ((tid & 31) == 0) red[g4 + ((tid >> 5) & 3)] = v;
    __syncthreads();
    float m = fmaxf(fmaxf(red[g4 + 0], red[g4 + 1]), fmaxf(red[g4 + 2], red[g4 + 3]));
    __syncthreads();
    return m;
}
__device__ __forceinline__ float grp_sum128(float v, float* red, int tid) {
    #pragma unroll
    for (int o = 16; o > 0; o >>= 1) v += __shfl_xor_sync(0xffffffffu, v, o);
    int g4 = (tid >> 7) * 4;
    if ((tid & 31) == 0) red[g4 + ((tid >> 5) & 3)] = v;
    __syncthreads();
    float m = (red[g4 + 0] + red[g4 + 1]) + (red[g4 + 2] + red[g4 + 3]);
    __syncthreads();
    return m;
}

// Gates GEMM slice: rows of WA (local) x 8 batches (oct) x k-chunk (kq).
// NKQ k-chunks, RT row slots, RPT rows/thread (stride RT). klen = k per chunk.
template<int NKQ, int RT, int RPT>
__device__ __forceinline__ void gemmA(const float* __restrict__ WA,
                                      const float* __restrict__ V,
                                      float* __restrict__ gb4, int nrows, int tid,
                                      int k0, int klen, bool accum)
{
    if (tid >= NKQ * 2 * RT) return;
    const int kq  = tid / (2 * RT);
    const int rem = tid - kq * (2 * RT);
    const int oct = rem & 1, rowg = rem >> 1;
    const int kb  = k0 + kq * klen;
    const float* Vb  = V + oct * (8 * KVP + 4) + kb;
    const float* Wp0 = WA + rowg * KVP + kb;
    const float* Wp1 = WA + (rowg + (RPT == 2 ? RT : 0)) * KVP + kb;
    unsigned long long a0[8], a1[8];
    #pragma unroll
    for (int j = 0; j < 8; j++) { a0[j] = 0ull; a1[j] = 0ull; }
    #pragma unroll 4
    for (int k = 0; k < klen; k += 4) {
        ulonglong2 w0 = *(const ulonglong2*)(Wp0 + k);
        ulonglong2 w1;
        if (RPT == 2) w1 = *(const ulonglong2*)(Wp1 + k);
        #pragma unroll
        for (int j = 0; j < 8; j++) {
            ulonglong2 v = *(const ulonglong2*)(Vb + j * KVP + k);
            a0[j] = ffma2_(w0.x, v.x, a0[j]);
            a0[j] = ffma2_(w0.y, v.y, a0[j]);
            if (RPT == 2) {
                a1[j] = ffma2_(w1.x, v.x, a1[j]);
                a1[j] = ffma2_(w1.y, v.y, a1[j]);
            }
        }
    }
    {
        float* gp = &gb4[(kq * nrows + rowg) * GBP + oct * 8];
        #pragma unroll
        for (int j = 0; j < 8; j++) { float s = hsum2_(a0[j]); gp[j] = accum ? gp[j] + s : s; }
    }
    if (RPT == 2) {
        float* gp = &gb4[(kq * nrows + rowg + RT) * GBP + oct * 8];
        #pragma unroll
        for (int j = 0; j < 8; j++) { float s = hsum2_(a1[j]); gp[j] = accum ? gp[j] + s : s; }
    }
}

__global__ void __launch_bounds__(NT, 1)
ntm_kernel(const float* __restrict__ X,
           const float* __restrict__ Wih, const float* __restrict__ Whh,
           const float* __restrict__ bl,
           const float* __restrict__ Whd, const float* __restrict__ bhd,
           const float* __restrict__ Wout, const float* __restrict__ bout,
           float* __restrict__ Y)
{
    const int tid = threadIdx.x, bx = blockIdx.x;
    const int b0 = (bx & 1) * 16;
    const bool isb = (bx < Bz);
    const int nunits = isb ? 2 : 10;
    const int nrows  = 4 * nunits;
    const int nkq    = isb ? 16 : 4;
    const int u_base = isb ? ((bx >> 1) * 2) : (32 + ((bx - Bz) >> 1) * 10);

    // ---- runtime smem layout ----
    float* WA  = sm;                       // nrows * KVP
    float* V   = WA + nrows * KVP;         // 16*KVP + 4 (skew)
    float* WB  = V + (16 * KVP + 4);       // 9 * WBP
    float* gb4 = WB + 9 * WBP;             // nkq * nrows * GBP
    float* bA  = gb4 + nkq * nrows * GBP;  // nrows
    float* bB  = bA + nrows;               // 12
    float* cst = bB + 12;                  // nunits*16
    float* red = cst + nunits * 16;        // 8
    float* scb = red + 8;                  // 16
    float* tail = scb + 16;
    // batch tail
    float* M  = tail;                 // 128*MP
    float* Mn = M + Nz * MP;          // 128
    float* wr = Mn + Nz;              // 128
    float* ww = wr + Nz;              // 128
    float* t1 = ww + Nz;              // 256
    float* pb = t1 + 256;             // 268
    float* kr = pb + Pz;              // 64
    float* kw = kr + Cz;              // 64
    float* eb = kw + Cz;              // 64
    float* ab = eb + Cz;              // 64
    // non-batch tail
    float* rbuf = tail;               // 64*32
    float* WoR  = rbuf + 2048;        // 3*64

    // ---------------- one-time staging ----------------
    for (int rr = 0; rr < nrows; rr++) {
        int q = rr / nunits, j = rr - q * nunits;
        int gr = q * Hz + u_base + j;
        for (int k = tid; k < KV; k += NT) {
            float v;
            if (k < 256)      v = Wih[gr * 320 + k];
            else if (k < 768) v = Whh[gr * Hz + (k - 256)];
            else              v = Wih[gr * 320 + 256 + (k - 768)];
            WA[rr * KVP + k] = v;
        }
    }
    if (tid < nrows) {
        int q = tid / nunits, j = tid - q * nunits;
        bA[tid] = bl[q * Hz + u_base + j];
    }
    const int baseB = (bx >> 1) * 9;
    const int cnt = (baseB >= 524) ? 0 : ((524 - baseB < 9) ? (524 - baseB) : 9);
    for (int rr = 0; rr < cnt; rr++) {
        int gr = baseB + rr;
        for (int k = tid; k < Hz; k += NT)
            WB[rr * WBP + k] = (gr < Pz) ? Whd[gr * Hz + k] : Wout[(gr - Pz) * 576 + k];
    }
    if (tid < cnt) {
        int gr = baseB + tid;
        bB[tid] = (gr < Pz) ? bhd[gr] : bout[gr - Pz];
    }
    if (!isb) {
        for (int i = tid; i < 3 * Cz; i += NT) {
            int o = (bx - Bz) * 3 + (i >> 6);
            if (o < Oz) WoR[i] = Wout[o * 576 + 512 + (i & 63)];
        }
    }
    for (int i = tid; i < 16 * KVP + 4; i += NT) V[i] = 0.f;
    if (tid < nunits * 16) cst[tid] = 0.f;
    if (isb) {
        for (int i = tid; i < Nz * Cz; i += NT) M[(i >> 6) * MP + (i & 63)] = 0.01f;
        if (tid < Nz) {
            float w0 = (tid == 0) ? 1.f : 0.f;
            wr[tid] = w0; ww[tid] = w0; Mn[tid] = 0.08f;
        }
    }
    unsigned gen0 = *((volatile unsigned*)&gs.flags[bx]);
    unsigned nb = 0;
    __syncthreads();

    // ---------------- prologue: stage x(0), A-main(0) ----------------
    for (int i = tid; i < 16 * Iz / 4; i += NT) {
        int b = i >> 6, c4 = (i & 63) << 2;
        *(float4*)&V[voffb(b) + c4] =
            *(const float4*)&X[((size_t)(b0 + b) * Sz + 0) * Iz + c4];
    }
    __syncthreads();
    if (isb) gemmA<16, 8, 1>(WA, V, gb4, nrows, tid, 0, 48, false);
    else     gemmA<4, 20, 2>(WA, V, gb4, nrows, tid, 0, 192, false);
    __syncthreads();

    // ---------------- recurrence ----------------
    for (int t = 0; t < Sz; t++) {
        // == phase 1: prefetch x(t+1) to regs; stage r(t-1) into V ==
        float4 xr[4];
        if (t + 1 < Sz) {
            #pragma unroll
            for (int q = 0; q < 4; q++) {
                int i = tid + q * NT, b = i >> 6, c4 = (i & 63) << 2;
                xr[q] = *(const float4*)&X[((size_t)(b0 + b) * Sz + (t + 1)) * Iz + c4];
            }
        }
        if (t > 0) {
            int b = tid >> 4, c4 = (tid & 15) << 2;
            *(float4*)&V[voffb(b) + 768 + c4] =
                *(const float4*)&gs.r[(b0 + b) * Cz + c4];
            __syncthreads();
        }
        // == phase 2: r-part of gates GEMM (accumulate into gb4) ==
        if (isb) gemmA<16, 8, 1>(WA, V, gb4, nrows, tid, 768, 4, true);
        else     gemmA<4, 20, 2>(WA, V, gb4, nrows, tid, 768, 16, true);
        __syncthreads();
        // == phase 3: LSTM; non-batch also D(t-1) ==
        if (tid < nunits * 16) {
            int j = tid >> 4, b = tid & 15;
            float G[4];
            #pragma unroll
            for (int g = 0; g < 4; g++) {
                int rr = g * nunits + j;
                float acc = bA[rr];
                for (int kq = 0; kq < nkq; kq++) acc += gb4[(kq * nrows + rr) * GBP + b];
                G[g] = acc;
            }
            float c = sg_(G[1]) * cst[tid] + sg_(G[0]) * tanhf(G[2]);
            float h = sg_(G[3]) * tanhf(c);
            cst[tid] = c;
            gs.h[(b0 + b) * Hz + u_base + j] = h;
        }
        if (!isb && t > 0) {
            for (int i = tid; i < Bz * Cz / 4; i += NT) {
                int b = i >> 4, c4 = (i & 15) << 2;
                float4 rv = *(const float4*)&gs.r[b * Cz + c4];
                rbuf[(c4 + 0) * 32 + b] = rv.x;
                rbuf[(c4 + 1) * 32 + b] = rv.y;
                rbuf[(c4 + 2) * 32 + b] = rv.z;
                rbuf[(c4 + 3) * 32 + b] = rv.w;
            }
            __syncthreads();
            if (tid < 96) {
                int oi = tid >> 5, b = tid & 31, o = (bx - Bz) * 3 + oi;
                if (o < Oz) {
                    float a0 = 0.f, a1 = 0.f;
                    const float* wo = &WoR[oi * Cz];
                    #pragma unroll
                    for (int c = 0; c < 64; c += 2) {
                        a0 = fmaf(rbuf[c * 32 + b], wo[c], a0);
                        a1 = fmaf(rbuf[(c + 1) * 32 + b], wo[c + 1], a1);
                    }
                    Y[((size_t)b * Sz + (t - 1)) * Oz + o] = gs.outh[b * Oz + o] + a0 + a1;
                }
            }
        }
        gbar(gen0, nb, tid, bx);   // bar1: h(t) visible

        // == phase 5: B(t) — p, outh ==
        for (int i = tid; i < 16 * Hz / 4; i += NT) {
            int b = i >> 7, c4 = (i & 127) << 2;
            *(float4*)&V[voffb(b) + 256 + c4] =
                *(const float4*)&gs.h[(b0 + b) * Hz + c4];
        }
        __syncthreads();
        if (tid < cnt * 16) {
            int rr = tid >> 4, b = tid & 15;
            const ulonglong2* Wp = (const ulonglong2*)&WB[rr * WBP];
            const ulonglong2* hp = (const ulonglong2*)&V[voffb(b) + 256];
            unsigned long long q0 = 0ull, q1 = 0ull, q2 = 0ull, q3 = 0ull;
            #pragma unroll 4
            for (int i = 0; i < 128; i += 2) {
                ulonglong2 w = Wp[i], v = hp[i];
                q0 = ffma2_(w.x, v.x, q0);
                q1 = ffma2_(w.y, v.y, q1);
                w = Wp[i + 1]; v = hp[i + 1];
                q2 = ffma2_(w.x, v.x, q2);
                q3 = ffma2_(w.y, v.y, q3);
            }
            float acc = (hsum2_(q0) + hsum2_(q1)) + (hsum2_(q2) + hsum2_(q3)) + bB[rr];
            int gr = baseB + rr;
            if (gr < Pz) gs.p[(b0 + b) * Pz + gr] = acc;
            else         gs.outh[(b0 + b) * Oz + (gr - Pz)] = acc;
        }
        gbar(gen0, nb, tid, bx);   // bar2: p, outh visible

        // == phase 7: batch CTAs: C(t); all: A-main(t+1) ==
        if (isb) {
            for (int i = tid; i < Pz; i += NT) pb[i] = gs.p[bx * Pz + i];
            __syncthreads();
            if (tid < 64) {
                kr[tid] = pb[tid];
                kw[tid] = pb[70 + tid];
                eb[tid] = sg_(pb[140 + tid]);
                ab[tid] = pb[204 + tid];
            }
            if ((tid & 127) == 0) {
                int hh = tid >> 7, o = hh ? 70 : 0;
                float kn0 = 0.f, kn1 = 0.f;
                for (int c = 0; c < 64; c += 2) {
                    kn0 = fmaf(pb[o + c], pb[o + c], kn0);
                    kn1 = fmaf(pb[o + c + 1], pb[o + c + 1], kn1);
                }
                float kn = sqrtf(kn0 + kn1);
                float s0 = pb[o + 66], s1 = pb[o + 67], s2 = pb[o + 68];
                float mx = fmaxf(s0, fmaxf(s1, s2));
                float e0 = expf(s0 - mx), e1 = expf(s1 - mx), e2 = expf(s2 - mx);
                float inv = 1.f / (e0 + e1 + e2);
                float* c_ = &scb[hh * 8];
                c_[0] = sp_(pb[o + 64]);
                c_[1] = sg_(pb[o + 65]);
                c_[2] = e0 * inv; c_[3] = e1 * inv; c_[4] = e2 * inv;
                c_[5] = 1.f + sp_(pb[o + 69]);
                c_[6] = 1.f / (kn + EPSF);
            }
            __syncthreads();
            {
                const int hh = tid >> 7, n = tid & 127;
                const float* kk = hh ? kw : kr;
                float* wprev = hh ? ww : wr;
                const float* c_ = &scb[hh * 8];
                float* t1h = &t1[hh * Nz];
                float d0 = 0.f, d1 = 0.f, d2 = 0.f, d3 = 0.f;
                const float* Mp = &M[n * MP];
                #pragma unroll
                for (int c = 0; c < 64; c += 16) {
                    float4 m, k4;
                    m = *(const float4*)(Mp + c);      k4 = *(const float4*)(kk + c);
                    d0 = fmaf(m.x, k4.x, d0); d0 = fmaf(m.y, k4.y, d0);
                    d0 = fmaf(m.z, k4.z, d0); d0 = fmaf(m.w, k4.w, d0);
                    m = *(const float4*)(Mp + c + 4);  k4 = *(const float4*)(kk + c + 4);
                    d1 = fmaf(m.x, k4.x, d1); d1 = fmaf(m.y, k4.y, d1);
                    d1 = fmaf(m.z, k4.z, d1); d1 = fmaf(m.w, k4.w, d1);
                    m = *(const float4*)(Mp + c + 8);  k4 = *(const float4*)(kk + c + 8);
                    d2 = fmaf(m.x, k4.x, d2); d2 = fmaf(m.y, k4.y, d2);
                    d2 = fmaf(m.z, k4.z, d2); d2 = fmaf(m.w, k4.w, d2);
                    m = *(const float4*)(Mp + c + 12); k4 = *(const float4*)(kk + c + 12);
                    d3 = fmaf(m.x, k4.x, d3); d3 = fmaf(m.y, k4.y, d3);
                    d3 = fmaf(m.z, k4.z, d3); d3 = fmaf(m.w, k4.w, d3);
                }
                float d = (d0 + d1) + (d2 + d3);
                float val = c_[0] * d / (Mn[n] + EPSF) * c_[6];
                float mx = grp_max128(val, red, tid);
                float ex = expf(val - mx);
                float sum = grp_sum128(ex, red, tid);
                float wc = ex / sum;
                t1h[n] = c_[1] * wc + (1.f - c_[1]) * wprev[n];
                __syncthreads();
                float ws = c_[2] * t1h[(n + 1) & 127]
                         + c_[3] * t1h[n]
                         + c_[4] * t1h[(n + 127) & 127];
                float wp = powf(ws + EPSF, c_[5]);
                float sw = grp_sum128(wp, red, tid);
                wprev[n] = wp / sw;
            }
            __syncthreads();
            if (tid < 128) {
                float wwn = ww[tid];
                float* Mp = &M[tid * MP];
                float n0 = 0.f, n1 = 0.f;
                #pragma unroll
                for (int c = 0; c < 64; c += 2) {
                    float m0 = Mp[c] * (1.f - wwn * eb[c]) + wwn * ab[c];
                    float m1 = Mp[c + 1] * (1.f - wwn * eb[c + 1]) + wwn * ab[c + 1];
                    Mp[c] = m0; Mp[c + 1] = m1;
                    n0 = fmaf(m0, m0, n0); n1 = fmaf(m1, m1, n1);
                }
                Mn[tid] = sqrtf(n0 + n1);
            }
            __syncthreads();
            {
                int q = tid >> 6, c = tid & 63;
                float a0 = 0.f, a1 = 0.f;
                #pragma unroll
                for (int n2 = 0; n2 < 32; n2 += 2) {
                    a0 = fmaf(wr[q * 32 + n2], M[(q * 32 + n2) * MP + c], a0);
                    a1 = fmaf(wr[q * 32 + n2 + 1], M[(q * 32 + n2 + 1) * MP + c], a1);
                }
                t1[q * 64 + c] = a0 + a1;
            }
            __syncthreads();
            if (tid < 64)
                gs.r[bx * Cz + tid] = (t1[tid] + t1[64 + tid]) + (t1[128 + tid] + t1[192 + tid]);
        }
        if (t + 1 < Sz) {
            #pragma unroll
            for (int q = 0; q < 4; q++) {
                int i = tid + q * NT, b = i >> 6, c4 = (i & 63) << 2;
                *(float4*)&V[voffb(b) + c4] = xr[q];
            }
            __syncthreads();
            if (isb) gemmA<16, 8, 1>(WA, V, gb4, nrows, tid, 0, 48, false);
            else     gemmA<4, 20, 2>(WA, V, gb4, nrows, tid, 0, 192, false);
        }
        gbar(gen0, nb, tid, bx);   // bar3: r(t) visible
    }

    // ---------------- epilogue: D(255) ----------------
    if (!isb) {
        for (int i = tid; i < Bz * Cz / 4; i += NT) {
            int b = i >> 4, c4 = (i & 15) << 2;
            float4 rv = *(const float4*)&gs.r[b * Cz + c4];
            rbuf[(c4 + 0) * 32 + b] = rv.x;
            rbuf[(c4 + 1) * 32 + b] = rv.y;
            rbuf[(c4 + 2) * 32 + b] = rv.z;
            rbuf[(c4 + 3) * 32 + b] = rv.w;
        }
        __syncthreads();
        if (tid < 96) {
            int oi = tid >> 5, b = tid & 31, o = (bx - Bz) * 3 + oi;
            if (o < Oz) {
                float a0 = 0.f, a1 = 0.f;
                const float* wo = &WoR[oi * Cz];
                #pragma unroll
                for (int c = 0; c < 64; c += 2) {
                    a0 = fmaf(rbuf[c * 32 + b], wo[c], a0);
                    a1 = fmaf(rbuf[(c + 1) * 32 + b], wo[c + 1], a1);
                }
                Y[((size_t)b * Sz + (Sz - 1)) * Oz + o] = gs.outh[b * Oz + o] + a0 + a1;
            }
        }
    }
}

extern "C" void kernel_launch(void* const* d_in, const int* in_sizes, int n_in,
                              void* d_out, int out_size) {
    (void)in_sizes; (void)n_in; (void)out_size;
    const float* X    = (const float*)d_in[0];
    const float* Wih  = (const float*)d_in[1];
    const float* Whh  = (const float*)d_in[2];
    const float* bl   = (const float*)d_in[3];
    const float* Whd  = (const float*)d_in[4];
    const float* bhd  = (const float*)d_in[5];
    const float* Wout = (const float*)d_in[6];
    const float* bout = (const float*)d_in[7];
    float* Y = (float*)d_out;

    cudaFuncSetAttribute(ntm_kernel, cudaFuncAttributeMaxDynamicSharedMemorySize,
                         SMEM_BYTES);
    ntm_kernel<<<GRID, NT, SMEM_BYTES>>>(X, Wih, Whh, bl, Whd, bhd, Wout, bout, Y);
}